// round 15
// baseline (speedup 1.0000x reference)
#include <cuda_runtime.h>
#include <cstdint>

#define HH      1024
#define NMODES  64
#define LLEN    2048
#define TPB     128
#define GRID    1024         // 1 head per CTA

// smem (dynamic):
//  Apack: kk(8) x [mt(2) x slot(8) x n3(4)] x 16B = 8 KB
//  Bpack: kk(8) x [w(4) x lane(32)] x 16B        = 16 KB
//  SC   : 10 fields x 64 (chunk,mode) x float2   = 5 KB
#define A_BYTES   8192
#define B_BYTES   16384
#define SC_BYTES  (10 * 64 * 8)
#define SMEM_BYTES (A_BYTES + B_BYTES + SC_BYTES)

__device__ __forceinline__ uint32_t smem_u32(const void* p) {
    uint32_t a;
    asm("{ .reg .u64 t; cvta.to.shared.u64 t, %1; cvt.u32.u64 %0, t; }" : "=r"(a) : "l"(p));
    return a;
}
__device__ __forceinline__ void sts128f(uint32_t a, float x, float y, float z, float w) {
    asm volatile("st.shared.v4.b32 [%0],{%1,%2,%3,%4};" :: "r"(a), "f"(x), "f"(y), "f"(z), "f"(w) : "memory");
}
__device__ __forceinline__ void lds128(uint32_t a, uint32_t& x, uint32_t& y, uint32_t& z, uint32_t& w) {
    asm volatile("ld.shared.v4.u32 {%0,%1,%2,%3},[%4];" : "=r"(x), "=r"(y), "=r"(z), "=r"(w) : "r"(a));
}
__device__ __forceinline__ void mma8(float* d,
                                     uint32_t a0, uint32_t a1, uint32_t a2, uint32_t a3,
                                     uint32_t b0, uint32_t b1) {
    asm volatile(
        "mma.sync.aligned.m16n8k8.row.col.f32.tf32.tf32.f32 "
        "{%0,%1,%2,%3},{%4,%5,%6,%7},{%8,%9},{%0,%1,%2,%3};"
        : "+f"(d[0]), "+f"(d[1]), "+f"(d[2]), "+f"(d[3])
        : "r"(a0), "r"(a1), "r"(a2), "r"(a3), "r"(b0), "r"(b1));
}
__device__ __forceinline__ void cmul(float& xr, float& xi, float br, float bi) {
    const float t = xr * br - xi * bi;
    xi = xr * bi + xi * br;
    xr = t;
}

__global__ __launch_bounds__(TPB, 7)   // 7 CTAs/SM, 148*7=1036 >= 1024: single wave
void ssd_tc_v15_kernel(
    const float* __restrict__ log_dt,
    const float* __restrict__ log_w_real,
    const float* __restrict__ w_imag,
    const float* __restrict__ C_re,
    const float* __restrict__ C_im,
    float* __restrict__ out)
{
    extern __shared__ __align__(16) char smem_raw[];
    const uint32_t aA = smem_u32(smem_raw);
    const uint32_t aB = aA + A_BYTES;
    float2* SC = reinterpret_cast<float2*>(smem_raw + A_BYTES + B_BYTES);  // SC[f*64 + (c<<5|m)]

    const int tid  = threadIdx.x;
    const int lane = tid & 31;
    const int warp = tid >> 5;
    const int m    = tid & 31;     // mode within chunk
    const int q    = tid >> 5;     // 0..3 : gen work split
    const int mt   = q & 1;        // A m-tile
    const int sh   = q >> 1;       // A slot half
    const int r4   = lane >> 2;
    const int c4   = lane & 3;

    const int kkg = m >> 2;        // this mode's k-group (0..7)
    const int n3  = m & 3;
    const uint32_t kx = (uint32_t)(kkg & 1) << 6;

    const int h = blockIdx.x;

    // ---------- Phase 0: consts for 64 (mode,chunk) pairs; ALL 128 threads ----------
    // Thread (pm, ph): ph=0 does z..z32 + Cmod; ph=1 does z64 (direct) .. z1024.
    {
        const int pm = tid & 63;                  // pair index = (chunk<<5)|mode
        const int ph = tid >> 6;                  // 0/1: low/high power half
        const float dt = expf(log_dt[h]);
        const float wr = -__expf(log_w_real[h * NMODES + pm]);
        const float wi = w_imag[h * NMODES + pm];
        const float ar = wr * dt;
        const float ai = wi * dt;

#define SQ_ { const float t_ = pr * pr - pi * pi; pi = 2.0f * pr * pi; pr = t_; }
        if (ph == 0) {
            float sn, cs;
            const float ez = expf(ar);            // accurate: amplified along chain
            sincosf(ai, &sn, &cs);                // accurate, small arg
            const float zr = ez * cs, zi = ez * sn;

            // 2*Cmod*(1+2^-10): bias-corrected for tf32 truncation
            const float inv = __fdividef(1.0f, wr * wr + wi * wi);
            const float zm  = zr - 1.0f;
            const float tr  = (zm * wr + zi * wi) * inv;
            const float ti  = (zi * wr - zm * wi) * inv;
            const float cre = C_re[h * NMODES + pm];
            const float cim = C_im[h * NMODES + pm];
            const float corr = 2.0f * (1.0f + 0.0009765625f);
            SC[9 * 64 + pm] = make_float2(corr * (cre * tr - cim * ti),
                                          corr * (cre * ti + cim * tr));
            SC[0 * 64 + pm] = make_float2(zr, zi);
            float pr = zr, pi = zi;
            SQ_ SQ_  SC[1 * 64 + pm] = make_float2(pr, pi);   // z^4
            SQ_      SC[2 * 64 + pm] = make_float2(pr, pi);   // z^8
            SQ_      SC[3 * 64 + pm] = make_float2(pr, pi);   // z^16
            SQ_      SC[4 * 64 + pm] = make_float2(pr, pi);   // z^32
        } else {
            float sn, cs;
            const float e64 = expf(ar * 64.0f);    // direct z^64 (accurate path)
            sincosf(ai * 64.0f, &sn, &cs);
            float pr = e64 * cs, pi = e64 * sn;
            SC[5 * 64 + pm] = make_float2(pr, pi);            // z^64
            SQ_ SQ_  SC[6 * 64 + pm] = make_float2(pr, pi);   // z^256
            SQ_      SC[7 * 64 + pm] = make_float2(pr, pi);   // z^512
            SQ_      SC[8 * 64 + pm] = make_float2(pr, pi);   // z^1024
        }
#undef SQ_
    }
    __syncthreads();

    float acc[16];
    #pragma unroll
    for (int i = 0; i < 16; i++) acc[i] = 0.0f;

    #pragma unroll 1
    for (int c = 0; c < 2; c++) {
        const int idx = (c << 5) | m;
        const float2 Z = SC[0 * 64 + idx];

        // ---------- A fragments: rows (16mt + 4sh + t, +8), step x z^64 ----------
        {
            const float2 Z64  = SC[5 * 64 + idx];
            const float2 Z512 = SC[7 * 64 + idx];
            const float2 U    = SC[9 * 64 + idx];
            float u1r = U.x, u1i = U.y;
            if (mt) { const float2 Z1k  = SC[8 * 64 + idx]; cmul(u1r, u1i, Z1k.x,  Z1k.y);  }
            if (sh) { const float2 Z256 = SC[6 * 64 + idx]; cmul(u1r, u1i, Z256.x, Z256.y); }
            float u2r = u1r, u2i = u1i;
            cmul(u2r, u2i, Z512.x, Z512.y);          // rows +8
            const uint32_t baseA = aA + (uint32_t)kkg * 1024 + (uint32_t)mt * 512 + (uint32_t)n3 * 16;
            #pragma unroll
            for (int t = 0; t < 4; t++) {
                const uint32_t s = (uint32_t)(4 * sh + t);
                sts128f(baseA + ((s * 64) ^ kx), u1r, u2r, u1i, u2i);
                cmul(u1r, u1i, Z64.x, Z64.y);
                cmul(u2r, u2i, Z64.x, Z64.y);
            }
        }

        // ---------- B fragments: quad chains b = 16q + {j, j+4, j+8, j+12} ----------
        // Bpack[kk][w][lane] = {Re(b), -Im(b), Re(b+8), -Im(b+8)}, b = 16w + r4, mode 4kk+c4
        {
            const float2 Z4 = SC[1 * 64 + idx];
            const float2 Z8 = SC[2 * 64 + idx];
            float a0r = 1.0f, a0i = 0.0f;
            if (q & 1) { const float2 Z16 = SC[3 * 64 + idx]; cmul(a0r, a0i, Z16.x, Z16.y); }
            if (q & 2) { const float2 Z32 = SC[4 * 64 + idx]; cmul(a0r, a0i, Z32.x, Z32.y); }
            float a1r = a0r, a1i = a0i; cmul(a1r, a1i, Z4.x, Z4.y);   // b+4
            float b0r = a0r, b0i = a0i; cmul(b0r, b0i, Z8.x, Z8.y);   // b+8
            float b1r = a1r, b1i = a1i; cmul(b1r, b1i, Z8.x, Z8.y);   // b+12
            const uint32_t baseB = aB + (uint32_t)kkg * 2048 + (uint32_t)q * 512 + (uint32_t)n3 * 16;
            #pragma unroll
            for (int j = 0; j < 4; j++) {
                sts128f(baseB + (((uint32_t)j * 64) ^ kx),       a0r, -a0i, b0r, -b0i);
                sts128f(baseB + (((uint32_t)(j + 4) * 64) ^ kx), a1r, -a1i, b1r, -b1i);
                cmul(a0r, a0i, Z.x, Z.y);
                cmul(a1r, a1i, Z.x, Z.y);
                cmul(b0r, b0i, Z.x, Z.y);
                cmul(b1r, b1i, Z.x, Z.y);
            }
        }
        __syncthreads();

        // ---------- GEMM chunk: 8 kk, accumulate; 3 LDS + 4 MMA per kk ----------
        const uint32_t rdA = aA + (uint32_t)lane * 16;
        const uint32_t rdB = aB + (uint32_t)warp * 512 + (uint32_t)lane * 16;

        #pragma unroll
        for (int kk = 0; kk < 8; kk++) {
            const uint32_t sw = (uint32_t)(kk & 1) << 6;

            uint32_t a00, a01, a02, a03, a10, a11, a12, a13;
            lds128((rdA ^ sw) + (uint32_t)kk * 1024,       a00, a01, a02, a03);
            lds128((rdA ^ sw) + (uint32_t)kk * 1024 + 512, a10, a11, a12, a13);

            uint32_t b00, b01, b10, b11;
            lds128((rdB ^ sw) + (uint32_t)kk * 2048, b00, b01, b10, b11);

            mma8(acc + 0,  a00, a01, a02, a03, b00, b01);
            mma8(acc + 4,  a00, a01, a02, a03, b10, b11);
            mma8(acc + 8,  a10, a11, a12, a13, b00, b01);
            mma8(acc + 12, a10, a11, a12, a13, b10, b11);
        }

        if (c == 0) __syncthreads();   // before chunk-1 gen overwrites smem
    }

    // ---------- store (l = 64*a + b) ----------
    float* op = out + (size_t)h * LLEN;
    #pragma unroll
    for (int m2 = 0; m2 < 2; m2++) {
        #pragma unroll
        for (int nt = 0; nt < 2; nt++) {
            const float* a = acc + (m2 * 2 + nt) * 4;
            const int row = 16 * m2 + r4;
            const int col = 16 * warp + 8 * nt + 2 * c4;
            *reinterpret_cast<float2*>(op + row * 64 + col)       = make_float2(a[0], a[1]);
            *reinterpret_cast<float2*>(op + (row + 8) * 64 + col) = make_float2(a[2], a[3]);
        }
    }
}

extern "C" void kernel_launch(void* const* d_in, const int* in_sizes, int n_in,
                              void* d_out, int out_size)
{
    const float* log_dt     = (const float*)d_in[0];
    const float* log_w_real = (const float*)d_in[1];
    const float* w_imag     = (const float*)d_in[2];
    const float* C_re       = (const float*)d_in[3];
    const float* C_im       = (const float*)d_in[4];
    float*       out        = (float*)d_out;

    cudaFuncSetAttribute(ssd_tc_v15_kernel,
                         cudaFuncAttributeMaxDynamicSharedMemorySize, SMEM_BYTES);
    ssd_tc_v15_kernel<<<GRID, TPB, SMEM_BYTES>>>(log_dt, log_w_real, w_imag, C_re, C_im, out);
}

// round 16
// speedup vs baseline: 1.2409x; 1.2409x over previous
#include <cuda_runtime.h>
#include <cstdint>

#define HH      1024
#define NMODES  64
#define LLEN    2048
#define TPB     128
#define GRID    1024         // 1 head per CTA

// smem (dynamic):
//  Apack: kstep(4) x mt(2) x slot(8) x c4(4) x 16B = 4 KB   (fp16x2 fragments)
//  Bpack: kstep(4) x w(4) x slot(8) x c4(4) x 16B  = 8 KB
//  SC   : 10 fields x 64 (chunk,mode) x float2     = 5 KB
#define A_BYTES   4096
#define B_BYTES   8192
#define SC_BYTES  (10 * 64 * 8)
#define SMEM_BYTES (A_BYTES + B_BYTES + SC_BYTES)

__device__ __forceinline__ uint32_t smem_u32(const void* p) {
    uint32_t a;
    asm("{ .reg .u64 t; cvta.to.shared.u64 t, %1; cvt.u32.u64 %0, t; }" : "=r"(a) : "l"(p));
    return a;
}
// pack (lo=re, hi=im) into f16x2 (PTX cvt: first source -> high half)
__device__ __forceinline__ uint32_t h2(float re, float im) {
    uint32_t d; asm("cvt.rn.f16x2.f32 %0,%1,%2;" : "=r"(d) : "f"(im), "f"(re)); return d;
}
__device__ __forceinline__ void sts64(uint32_t a, uint32_t x, uint32_t y) {
    asm volatile("st.shared.v2.u32 [%0],{%1,%2};" :: "r"(a), "r"(x), "r"(y) : "memory");
}
__device__ __forceinline__ void lds128(uint32_t a, uint32_t& x, uint32_t& y, uint32_t& z, uint32_t& w) {
    asm volatile("ld.shared.v4.u32 {%0,%1,%2,%3},[%4];" : "=r"(x), "=r"(y), "=r"(z), "=r"(w) : "r"(a));
}
__device__ __forceinline__ void mma16(float* d,
                                      uint32_t a0, uint32_t a1, uint32_t a2, uint32_t a3,
                                      uint32_t b0, uint32_t b1) {
    asm volatile(
        "mma.sync.aligned.m16n8k16.row.col.f32.f16.f16.f32 "
        "{%0,%1,%2,%3},{%4,%5,%6,%7},{%8,%9},{%0,%1,%2,%3};"
        : "+f"(d[0]), "+f"(d[1]), "+f"(d[2]), "+f"(d[3])
        : "r"(a0), "r"(a1), "r"(a2), "r"(a3), "r"(b0), "r"(b1));
}
__device__ __forceinline__ void cmul(float& xr, float& xi, float br, float bi) {
    const float t = xr * br - xi * bi;
    xi = xr * bi + xi * br;
    xr = t;
}

__global__ __launch_bounds__(TPB, 7)   // 7 CTAs/SM, 148*7=1036 >= 1024: single wave
void ssd_tc_v16_kernel(
    const float* __restrict__ log_dt,
    const float* __restrict__ log_w_real,
    const float* __restrict__ w_imag,
    const float* __restrict__ C_re,
    const float* __restrict__ C_im,
    float* __restrict__ out)
{
    extern __shared__ __align__(16) char smem_raw[];
    const uint32_t aA = smem_u32(smem_raw);
    const uint32_t aB = aA + A_BYTES;
    float2* SC = reinterpret_cast<float2*>(smem_raw + A_BYTES + B_BYTES);  // SC[f*64 + (c<<5|m)]

    const int tid  = threadIdx.x;
    const int lane = tid & 31;
    const int warp = tid >> 5;
    const int m    = tid & 31;     // mode within chunk
    const int q    = tid >> 5;     // 0..3 : gen work split
    const int mt   = q & 1;        // A m-tile
    const int sh   = q >> 1;       // A slot half
    const int r4   = lane >> 2;
    const int c4   = lane & 3;

    const int kstep = m >> 3;      // this mode's k16-step (0..3)
    const int c4g   = m & 3;       // fragment k-pair group
    const int halfm = (m >> 2) & 1;// low/high half of 16B granule

    const int h = blockIdx.x;

    // ---------- Phase 0: consts for all 64 (mode, chunk) pairs, computed ONCE ----------
    if (tid < 64) {
        const int n0 = tid;                       // n = chunk*32 + mode, tid == (c<<5)|m
        const float dt = expf(log_dt[h]);
        const float wr = -__expf(log_w_real[h * NMODES + n0]);
        const float wi = w_imag[h * NMODES + n0];
        const float ar = wr * dt;
        const float ai = wi * dt;

        float sn, cs;
        const float ez = expf(ar);                // accurate: amplified along chain
        sincosf(ai, &sn, &cs);                    // accurate, small arg
        const float zr = ez * cs, zi = ez * sn;

        // 2*Cmod (no bias correction needed: f16x2 pack is round-to-nearest)
        const float inv = __fdividef(1.0f, wr * wr + wi * wi);
        const float zm  = zr - 1.0f;
        const float tr  = (zm * wr + zi * wi) * inv;
        const float ti  = (zi * wr - zm * wi) * inv;
        const float cre = C_re[h * NMODES + n0];
        const float cim = C_im[h * NMODES + n0];
        const float ur = 2.0f * (cre * tr - cim * ti);
        const float ui = 2.0f * (cre * ti + cim * tr);

        float pr = zr, pi = zi;
        SC[0 * 64 + tid] = make_float2(zr, zi);
#define SQ_ { const float t_ = pr * pr - pi * pi; pi = 2.0f * pr * pi; pr = t_; }
        SQ_ SQ_      SC[1 * 64 + tid] = make_float2(pr, pi);   // z^4
        SQ_          SC[2 * 64 + tid] = make_float2(pr, pi);   // z^8
        SQ_          SC[3 * 64 + tid] = make_float2(pr, pi);   // z^16
        SQ_          SC[4 * 64 + tid] = make_float2(pr, pi);   // z^32
        SQ_          SC[5 * 64 + tid] = make_float2(pr, pi);   // z^64
        SQ_ SQ_      SC[6 * 64 + tid] = make_float2(pr, pi);   // z^256
        SQ_          SC[7 * 64 + tid] = make_float2(pr, pi);   // z^512
        SQ_          SC[8 * 64 + tid] = make_float2(pr, pi);   // z^1024
#undef SQ_
        SC[9 * 64 + tid] = make_float2(ur, ui);
    }
    __syncthreads();

    float acc[16];
    #pragma unroll
    for (int i = 0; i < 16; i++) acc[i] = 0.0f;

    #pragma unroll 1
    for (int c = 0; c < 2; c++) {
        const int idx = (c << 5) | m;
        const float2 Z = SC[0 * 64 + idx];

        // ---------- A fragments: rows (16mt + 4sh + t, +8), step x z^64 ----------
        // granule[kstep][mt][slot][c4g]: {mode c4g rows(r,r+8) | mode c4g+4 rows(r,r+8)}
        {
            const float2 Z64  = SC[5 * 64 + idx];
            const float2 Z512 = SC[7 * 64 + idx];
            const float2 U    = SC[9 * 64 + idx];
            float u1r = U.x, u1i = U.y;
            if (mt) { const float2 Z1k  = SC[8 * 64 + idx]; cmul(u1r, u1i, Z1k.x,  Z1k.y);  }
            if (sh) { const float2 Z256 = SC[6 * 64 + idx]; cmul(u1r, u1i, Z256.x, Z256.y); }
            float u2r = u1r, u2i = u1i;
            cmul(u2r, u2i, Z512.x, Z512.y);          // rows +8
            const uint32_t baseA = aA + (uint32_t)kstep * 1024 + (uint32_t)mt * 512
                                      + (uint32_t)c4g * 16 + (uint32_t)halfm * 8;
            #pragma unroll
            for (int t = 0; t < 4; t++) {
                const uint32_t s = (uint32_t)((4 * sh + t) ^ kstep);
                sts64(baseA + s * 64, h2(u1r, u1i), h2(u2r, u2i));
                cmul(u1r, u1i, Z64.x, Z64.y);
                cmul(u2r, u2i, Z64.x, Z64.y);
            }
        }

        // ---------- B fragments: quad chains, cols 16q + {j, j+4, j+8, j+12} ----------
        // granule[kstep][w][slot][c4g]: {mode c4g cols(b,b+8) | mode c4g+4 cols(b,b+8)}, conj packed
        {
            const float2 Z4 = SC[1 * 64 + idx];
            const float2 Z8 = SC[2 * 64 + idx];
            float a0r = 1.0f, a0i = 0.0f;
            if (q & 1) { const float2 Z16 = SC[3 * 64 + idx]; cmul(a0r, a0i, Z16.x, Z16.y); }
            if (q & 2) { const float2 Z32 = SC[4 * 64 + idx]; cmul(a0r, a0i, Z32.x, Z32.y); }
            float a1r = a0r, a1i = a0i; cmul(a1r, a1i, Z4.x, Z4.y);   // col +4
            float b0r = a0r, b0i = a0i; cmul(b0r, b0i, Z8.x, Z8.y);   // col +8
            float b1r = a1r, b1i = a1i; cmul(b1r, b1i, Z8.x, Z8.y);   // col +12
            const uint32_t baseB = aB + (uint32_t)kstep * 2048 + (uint32_t)q * 512
                                      + (uint32_t)c4g * 16 + (uint32_t)halfm * 8;
            #pragma unroll
            for (int j = 0; j < 4; j++) {
                sts64(baseB + (uint32_t)(j ^ kstep) * 64,       h2(a0r, -a0i), h2(b0r, -b0i));
                sts64(baseB + (uint32_t)((j + 4) ^ kstep) * 64, h2(a1r, -a1i), h2(b1r, -b1i));
                cmul(a0r, a0i, Z.x, Z.y);
                cmul(a1r, a1i, Z.x, Z.y);
                cmul(b0r, b0i, Z.x, Z.y);
                cmul(b1r, b1i, Z.x, Z.y);
            }
        }
        __syncthreads();

        // ---------- GEMM chunk: 4 k16-steps; 3 LDS + 4 MMA per step ----------
        const uint32_t rdA = aA + (uint32_t)c4 * 16;
        const uint32_t rdB = aB + (uint32_t)warp * 512 + (uint32_t)c4 * 16;

        #pragma unroll
        for (int ks = 0; ks < 4; ks++) {
            const uint32_t rsw = (uint32_t)(r4 ^ ks) * 64;

            uint32_t a00, a01, a02, a03, a10, a11, a12, a13;
            lds128(rdA + (uint32_t)ks * 1024 + rsw,       a00, a01, a02, a03);
            lds128(rdA + (uint32_t)ks * 1024 + 512 + rsw, a10, a11, a12, a13);

            uint32_t bx, by, bz, bw;
            lds128(rdB + (uint32_t)ks * 2048 + rsw, bx, by, bz, bw);
            // bx = mode c4 col r4 | by = mode c4 col r4+8 | bz = mode c4+4 col r4 | bw = c4+4 col r4+8

            mma16(acc + 0,  a00, a01, a02, a03, bx, bz);   // mt0, nt0
            mma16(acc + 4,  a00, a01, a02, a03, by, bw);   // mt0, nt1
            mma16(acc + 8,  a10, a11, a12, a13, bx, bz);   // mt1, nt0
            mma16(acc + 12, a10, a11, a12, a13, by, bw);   // mt1, nt1
        }

        if (c == 0) __syncthreads();   // before chunk-1 gen overwrites smem
    }

    // ---------- store (l = 64*a + b) ----------
    float* op = out + (size_t)h * LLEN;
    #pragma unroll
    for (int m2 = 0; m2 < 2; m2++) {
        #pragma unroll
        for (int nt = 0; nt < 2; nt++) {
            const float* a = acc + (m2 * 2 + nt) * 4;
            const int row = 16 * m2 + r4;
            const int col = 16 * warp + 8 * nt + 2 * c4;
            *reinterpret_cast<float2*>(op + row * 64 + col)       = make_float2(a[0], a[1]);
            *reinterpret_cast<float2*>(op + (row + 8) * 64 + col) = make_float2(a[2], a[3]);
        }
    }
}

extern "C" void kernel_launch(void* const* d_in, const int* in_sizes, int n_in,
                              void* d_out, int out_size)
{
    const float* log_dt     = (const float*)d_in[0];
    const float* log_w_real = (const float*)d_in[1];
    const float* w_imag     = (const float*)d_in[2];
    const float* C_re       = (const float*)d_in[3];
    const float* C_im       = (const float*)d_in[4];
    float*       out        = (float*)d_out;

    cudaFuncSetAttribute(ssd_tc_v16_kernel,
                         cudaFuncAttributeMaxDynamicSharedMemorySize, SMEM_BYTES);
    ssd_tc_v16_kernel<<<GRID, TPB, SMEM_BYTES>>>(log_dt, log_w_real, w_imag, C_re, C_im, out);
}

// round 17
// speedup vs baseline: 1.4083x; 1.1349x over previous
#include <cuda_runtime.h>
#include <cstdint>

#define HH      1024
#define NMODES  64
#define LLEN    2048
#define TPB     128
#define GRID    1024         // 1 head per CTA

// smem (dynamic), full K=128 resident:
//  Apack: kstep(8) x mt(2) x slot(8) x c4(4) x 16B = 8 KB
//  Bpack: kstep(8) x w(4) x slot(8) x c4(4) x 16B  = 16 KB
#define A_BYTES   8192
#define B_BYTES   16384
#define SMEM_BYTES (A_BYTES + B_BYTES)

__device__ __forceinline__ uint32_t smem_u32(const void* p) {
    uint32_t a;
    asm("{ .reg .u64 t; cvta.to.shared.u64 t, %1; cvt.u32.u64 %0, t; }" : "=r"(a) : "l"(p));
    return a;
}
// pack (lo=re, hi=im) into f16x2 (PTX cvt: first source -> high half)
__device__ __forceinline__ uint32_t h2(float re, float im) {
    uint32_t d; asm("cvt.rn.f16x2.f32 %0,%1,%2;" : "=r"(d) : "f"(im), "f"(re)); return d;
}
__device__ __forceinline__ void sts64(uint32_t a, uint32_t x, uint32_t y) {
    asm volatile("st.shared.v2.u32 [%0],{%1,%2};" :: "r"(a), "r"(x), "r"(y) : "memory");
}
__device__ __forceinline__ void lds128(uint32_t a, uint32_t& x, uint32_t& y, uint32_t& z, uint32_t& w) {
    asm volatile("ld.shared.v4.u32 {%0,%1,%2,%3},[%4];" : "=r"(x), "=r"(y), "=r"(z), "=r"(w) : "r"(a));
}
__device__ __forceinline__ void mma16(float* d,
                                      uint32_t a0, uint32_t a1, uint32_t a2, uint32_t a3,
                                      uint32_t b0, uint32_t b1) {
    asm volatile(
        "mma.sync.aligned.m16n8k16.row.col.f32.f16.f16.f32 "
        "{%0,%1,%2,%3},{%4,%5,%6,%7},{%8,%9},{%0,%1,%2,%3};"
        : "+f"(d[0]), "+f"(d[1]), "+f"(d[2]), "+f"(d[3])
        : "r"(a0), "r"(a1), "r"(a2), "r"(a3), "r"(b0), "r"(b1));
}
__device__ __forceinline__ void cmul(float& xr, float& xi, float br, float bi) {
    const float t = xr * br - xi * bi;
    xi = xr * bi + xi * br;
    xr = t;
}

__global__ __launch_bounds__(TPB, 7)   // 7 CTAs/SM, 148*7=1036 >= 1024: single wave
void ssd_tc_v17_kernel(
    const float* __restrict__ log_dt,
    const float* __restrict__ log_w_real,
    const float* __restrict__ w_imag,
    const float* __restrict__ C_re,
    const float* __restrict__ C_im,
    float* __restrict__ out)
{
    extern __shared__ __align__(16) char smem_raw[];
    const uint32_t aA = smem_u32(smem_raw);
    const uint32_t aB = aA + A_BYTES;

    const int tid  = threadIdx.x;
    const int lane = tid & 31;
    const int warp = tid >> 5;
    const int pm   = tid & 63;     // mode (0..63), duplicated across ph
    const int ph   = tid >> 6;     // 0/1: row/col half owner
    const int r4   = lane >> 2;
    const int c4   = lane & 3;

    const int kstep = pm >> 3;     // k16-step of this mode (0..7)
    const int c4g   = pm & 3;
    const int halfm = (pm >> 2) & 1;

    const int h = blockIdx.x;

    // ---------- inline per-mode constants (2x duplicated; no table, no barrier) ----------
    const float dt = expf(log_dt[h]);
    const float wr = -__expf(log_w_real[h * NMODES + pm]);
    const float wi = w_imag[h * NMODES + pm];
    const float ar = wr * dt;
    const float ai = wi * dt;

    float sn, cs;
    const float ez = expf(ar);                // accurate: amplified along chain
    sincosf(ai, &sn, &cs);                    // accurate, small arg
    const float zr = ez * cs, zi = ez * sn;

    // 2*Cmod = 2*C*(z-1)/w  (f16x2 RN pack -> no bias correction needed)
    const float inv = __fdividef(1.0f, wr * wr + wi * wi);
    const float zm  = zr - 1.0f;
    const float trm = (zm * wr + zi * wi) * inv;
    const float tim = (zi * wr - zm * wi) * inv;
    const float cre = C_re[h * NMODES + pm];
    const float cim = C_im[h * NMODES + pm];
    const float ur0 = 2.0f * (cre * trm - cim * tim);
    const float ui0 = 2.0f * (cre * tim + cim * trm);

    float pr = zr, pi = zi;
#define SQ_ { const float t_ = pr * pr - pi * pi; pi = 2.0f * pr * pi; pr = t_; }
    SQ_ SQ_   const float z4r = pr,   z4i = pi;     // z^4
    SQ_       const float z8r = pr,   z8i = pi;     // z^8
    SQ_       const float z16r = pr,  z16i = pi;    // z^16
    SQ_       const float z32r = pr,  z32i = pi;    // z^32
    SQ_       const float z64r = pr,  z64i = pi;    // z^64
    SQ_ SQ_ SQ_ const float z512r = pr, z512i = pi; // z^512
    SQ_                                              // z^1024 in (pr,pi)
#undef SQ_

    // ---------- A fragments: rows (16ph + t, +8), t = 0..7, step x z^64 ----------
    {
        float u1r = ur0, u1i = ui0;
        if (ph) cmul(u1r, u1i, pr, pi);           // x z^1024
        float u2r = u1r, u2i = u1i;
        cmul(u2r, u2i, z512r, z512i);             // rows +8
        const uint32_t baseA = aA + (uint32_t)kstep * 1024 + (uint32_t)ph * 512
                                  + (uint32_t)c4g * 16 + (uint32_t)halfm * 8;
        #pragma unroll
        for (int t = 0; t < 8; t++) {
            sts64(baseA + (uint32_t)((t ^ kstep) & 7) * 64, h2(u1r, u1i), h2(u2r, u2i));
            cmul(u1r, u1i, z64r, z64i);
            cmul(u2r, u2i, z64r, z64i);
        }
    }

    // ---------- B fragments: cols [32ph, 32ph+32), 8 parallel chains, 4 iters ----------
    // span0 (w=2ph):   chains a0(c+0) a1(c+4) b0(c+8) b1(c+12),  c = 32ph
    // span1 (w=2ph+1): same x z^16
    {
        float a0r = 1.0f, a0i = 0.0f;
        if (ph) { a0r = z32r; a0i = z32i; }
        float a1r = a0r, a1i = a0i; cmul(a1r, a1i, z4r, z4i);
        float b0r = a0r, b0i = a0i; cmul(b0r, b0i, z8r, z8i);
        float b1r = a1r, b1i = a1i; cmul(b1r, b1i, z8r, z8i);
        float c0r = a0r, c0i = a0i; cmul(c0r, c0i, z16r, z16i);
        float c1r = a1r, c1i = a1i; cmul(c1r, c1i, z16r, z16i);
        float c2r = b0r, c2i = b0i; cmul(c2r, c2i, z16r, z16i);
        float c3r = b1r, c3i = b1i; cmul(c3r, c3i, z16r, z16i);

        const uint32_t baseB0 = aB + (uint32_t)kstep * 2048 + (uint32_t)(2 * ph) * 512
                                   + (uint32_t)c4g * 16 + (uint32_t)halfm * 8;
        const uint32_t baseB1 = baseB0 + 512;
        #pragma unroll
        for (int j = 0; j < 4; j++) {
            const uint32_t s0 = (uint32_t)((j ^ kstep) & 7) * 64;
            const uint32_t s1 = (uint32_t)(((j + 4) ^ kstep) & 7) * 64;
            sts64(baseB0 + s0, h2(a0r, -a0i), h2(b0r, -b0i));
            sts64(baseB0 + s1, h2(a1r, -a1i), h2(b1r, -b1i));
            sts64(baseB1 + s0, h2(c0r, -c0i), h2(c2r, -c2i));
            sts64(baseB1 + s1, h2(c1r, -c1i), h2(c3r, -c3i));
            cmul(a0r, a0i, zr, zi);  cmul(a1r, a1i, zr, zi);
            cmul(b0r, b0i, zr, zi);  cmul(b1r, b1i, zr, zi);
            cmul(c0r, c0i, zr, zi);  cmul(c1r, c1i, zr, zi);
            cmul(c2r, c2i, zr, zi);  cmul(c3r, c3i, zr, zi);
        }
    }
    __syncthreads();   // the ONLY barrier

    // ---------- GEMM 32x64x128: 8 k16-steps; 3 LDS + 4 MMA per step ----------
    float acc[16];
    #pragma unroll
    for (int i = 0; i < 16; i++) acc[i] = 0.0f;

    const uint32_t rdA = aA + (uint32_t)c4 * 16;
    const uint32_t rdB = aB + (uint32_t)warp * 512 + (uint32_t)c4 * 16;

    #pragma unroll
    for (int ks = 0; ks < 8; ks++) {
        const uint32_t rsw = (uint32_t)((r4 ^ ks) & 7) * 64;

        uint32_t a00, a01, a02, a03, a10, a11, a12, a13;
        lds128(rdA + (uint32_t)ks * 1024 + rsw,       a00, a01, a02, a03);
        lds128(rdA + (uint32_t)ks * 1024 + 512 + rsw, a10, a11, a12, a13);

        uint32_t bx, by, bz, bw;
        lds128(rdB + (uint32_t)ks * 2048 + rsw, bx, by, bz, bw);

        mma16(acc + 0,  a00, a01, a02, a03, bx, bz);   // mt0, nt0
        mma16(acc + 4,  a00, a01, a02, a03, by, bw);   // mt0, nt1
        mma16(acc + 8,  a10, a11, a12, a13, bx, bz);   // mt1, nt0
        mma16(acc + 12, a10, a11, a12, a13, by, bw);   // mt1, nt1
    }

    // ---------- store (l = 64*a + b) ----------
    float* op = out + (size_t)h * LLEN;
    #pragma unroll
    for (int m2 = 0; m2 < 2; m2++) {
        #pragma unroll
        for (int nt = 0; nt < 2; nt++) {
            const float* a = acc + (m2 * 2 + nt) * 4;
            const int row = 16 * m2 + r4;
            const int col = 16 * warp + 8 * nt + 2 * c4;
            *reinterpret_cast<float2*>(op + row * 64 + col)       = make_float2(a[0], a[1]);
            *reinterpret_cast<float2*>(op + (row + 8) * 64 + col) = make_float2(a[2], a[3]);
        }
    }
}

extern "C" void kernel_launch(void* const* d_in, const int* in_sizes, int n_in,
                              void* d_out, int out_size)
{
    const float* log_dt     = (const float*)d_in[0];
    const float* log_w_real = (const float*)d_in[1];
    const float* w_imag     = (const float*)d_in[2];
    const float* C_re       = (const float*)d_in[3];
    const float* C_im       = (const float*)d_in[4];
    float*       out        = (float*)d_out;

    cudaFuncSetAttribute(ssd_tc_v17_kernel,
                         cudaFuncAttributeMaxDynamicSharedMemorySize, SMEM_BYTES);
    ssd_tc_v17_kernel<<<GRID, TPB, SMEM_BYTES>>>(log_dt, log_w_real, w_imag, C_re, C_im, out);
}